// round 1
// baseline (speedup 1.0000x reference)
#include <cuda_runtime.h>
#include <cstdint>

// Problem constants (fixed by the reference setup_inputs)
#define NS   16      // n_samples
#define NP   2048    // n_points
#define DIM  64      // dims
#define KNN  16      // K
#define TILE 128     // db points per smem tile
#define BLOCK 128    // threads per block (1 query per thread)
#define ROWF 68      // padded floats per smem row (68*4 = 272 B = 17 x 16B)
#define ROWB (ROWF * 4)
#define NTOT (NS * NP * KNN)   // 524288 elements per output tensor

// ---- packed f32x2 helpers (sm_103a) ------------------------------------
__device__ __forceinline__ unsigned long long pk2(float x, float y) {
    unsigned long long r;
    asm("mov.b64 %0, {%1, %2};" : "=l"(r) : "f"(x), "f"(y));
    return r;
}
__device__ __forceinline__ void unpk2(float& lo, float& hi, unsigned long long v) {
    asm("mov.b64 {%0, %1}, %2;" : "=f"(lo), "=f"(hi) : "l"(v));
}
__device__ __forceinline__ unsigned long long fma2(unsigned long long a,
                                                   unsigned long long b,
                                                   unsigned long long c) {
    unsigned long long d;
    asm("fma.rn.f32x2 %0, %1, %2, %3;" : "=l"(d) : "l"(a), "l"(b), "l"(c));
    return d;
}
__device__ __forceinline__ unsigned long long add2(unsigned long long a,
                                                   unsigned long long b) {
    unsigned long long d;
    asm("add.rn.f32x2 %0, %1, %2;" : "=l"(d) : "l"(a), "l"(b));
    return d;
}
// 16B shared load as two packed f32x2 (address must be 16B aligned)
__device__ __forceinline__ void lds2x64(unsigned long long& a, unsigned long long& b,
                                        unsigned addr) {
    asm volatile("ld.shared.v2.b64 {%0, %1}, [%2];"
                 : "=l"(a), "=l"(b) : "r"(addr));
}

__global__ void __launch_bounds__(BLOCK, 2)
knn_graph_kernel(const float* __restrict__ h, float* __restrict__ out,
                 int write_edges) {
    __shared__ __align__(16) float smem[TILE * ROWF];  // padded db tile
    __shared__ float sx2[TILE];                        // db squared norms

    const int b    = blockIdx.x / (NP / BLOCK);
    const int qblk = (blockIdx.x % (NP / BLOCK)) * BLOCK;
    const int q    = qblk + threadIdx.x;
    const float* hb = h + (size_t)b * NP * DIM;

    // ---- load query vector into packed register pairs, compute |q|^2 ----
    unsigned long long qp[DIM / 2];
    float x2q = 0.0f;
    {
        const float4* gq = (const float4*)(hb + (size_t)q * DIM);
#pragma unroll
        for (int i = 0; i < DIM / 4; i++) {
            float4 v = gq[i];
            x2q = fmaf(v.x, v.x, x2q);
            x2q = fmaf(v.y, v.y, x2q);
            x2q = fmaf(v.z, v.z, x2q);
            x2q = fmaf(v.w, v.w, x2q);
            qp[2 * i]     = pk2(v.x, v.y);
            qp[2 * i + 1] = pk2(v.z, v.w);
        }
    }

    // ---- top-K state: sorted ascending, register-resident ----
    float bd[KNN];
    int   bi[KNN];
#pragma unroll
    for (int k = 0; k < KNN; k++) { bd[k] = __int_as_float(0x7f800000); bi[k] = 0; }

    const unsigned sbase = (unsigned)__cvta_generic_to_shared(smem);

    for (int t = 0; t < NP / TILE; t++) {
        __syncthreads();  // previous tile fully consumed
        // cooperative coalesced tile load with row padding
        {
            const float4* gt = (const float4*)(hb + (size_t)t * TILE * DIM);
#pragma unroll
            for (int i = 0; i < (TILE * DIM / 4) / BLOCK; i++) {  // 16 iters
                int idx = i * BLOCK + threadIdx.x;
                int row = idx >> 4;        // DIM/4 = 16 float4 per row
                int col = idx & 15;
                ((float4*)smem)[row * (ROWF / 4) + col] = gt[idx];
            }
        }
        __syncthreads();
        // per-row squared norms (one row per thread; TILE == BLOCK)
        {
            const float4* rp = (const float4*)(smem + threadIdx.x * ROWF);
            float s = 0.0f;
#pragma unroll
            for (int i = 0; i < DIM / 4; i++) {
                float4 v = rp[i];
                s = fmaf(v.x, v.x, s);
                s = fmaf(v.y, v.y, s);
                s = fmaf(v.z, v.z, s);
                s = fmaf(v.w, v.w, s);
            }
            sx2[threadIdx.x] = s;
        }
        __syncthreads();

        // ---- main candidate loop ----
        for (int j = 0; j < TILE; j++) {
            const unsigned rb = sbase + j * ROWB;
            unsigned long long a0 = 0ull, a1 = 0ull, a2 = 0ull, a3 = 0ull;
#pragma unroll
            for (int i = 0; i < DIM / 4; i += 2) {  // 8 iters, 4x 16B chunks
                unsigned long long v0, v1, v2, v3;
                lds2x64(v0, v1, rb + i * 16);
                lds2x64(v2, v3, rb + i * 16 + 16);
                a0 = fma2(qp[2 * i + 0], v0, a0);
                a1 = fma2(qp[2 * i + 1], v1, a1);
                a2 = fma2(qp[2 * i + 2], v2, a2);
                a3 = fma2(qp[2 * i + 3], v3, a3);
            }
            float lo, hi;
            unpk2(lo, hi, add2(add2(a0, a1), add2(a2, a3)));
            const float dot  = lo + hi;
            const float dist = fmaf(-2.0f, dot, x2q + sx2[j]);

            if (dist < bd[KNN - 1]) {
                bd[KNN - 1] = dist;
                bi[KNN - 1] = t * TILE + j;
#pragma unroll
                for (int s = KNN - 1; s > 0; --s) {
                    if (bd[s] < bd[s - 1]) {  // strict: keeps lower index first on ties
                        float td = bd[s - 1]; bd[s - 1] = bd[s]; bd[s] = td;
                        int   ti = bi[s - 1]; bi[s - 1] = bi[s]; bi[s] = ti;
                    }
                }
            }
        }
    }

    // ---- write outputs: [knn_dist | dst | src] as f32 ----
    const size_t o   = ((size_t)b * NP + q) * KNN;
    const int    off = b * NP;
#pragma unroll
    for (int k = 0; k < KNN; k++) out[o + k] = bd[k];
    if (write_edges) {
#pragma unroll
        for (int k = 0; k < KNN; k++)
            out[(size_t)NTOT + o + k] = (float)(bi[k] + off);
#pragma unroll
        for (int k = 0; k < KNN; k++)
            out[(size_t)2 * NTOT + o + k] = (float)(q + off);
    }
}

extern "C" void kernel_launch(void* const* d_in, const int* in_sizes, int n_in,
                              void* d_out, int out_size) {
    const float* h = (const float*)d_in[0];
    // out_size tells us whether the harness wants only knn_dist (524288) or
    // the full concatenation [knn_dist | dst | src] (1572864).
    int write_edges = (out_size >= 3 * NTOT) ? 1 : 0;
    knn_graph_kernel<<<NS * (NP / BLOCK), BLOCK>>>(h, (float*)d_out, write_edges);
}

// round 4
// speedup vs baseline: 1.3759x; 1.3759x over previous
#include <cuda_runtime.h>
#include <cstdint>

// Problem constants (fixed by reference setup_inputs)
#define NS    16
#define NP    2048
#define DIM   64
#define KNN   16
#define BLOCK 128
#define QB    256              // queries per CTA (2 per thread)
#define HALF  2                // DB split factor
#define CAND  (NP / HALF)      // 1024 candidates per CTA
#define TILE  128              // candidates per smem tile
#define ROWF  68               // padded floats per smem row (272 B)
#define ROWB  (ROWF * 4)
#define NTOT  (NS * NP * KNN)  // 524288
#define BUFS  4                // ring-buffer slots per query per thread

typedef unsigned long long ull;

// Partial top-K scratch (static device arrays — no allocation)
__device__ float g_pd[HALF][NS * NP][KNN];
__device__ int   g_pi[HALF][NS * NP][KNN];

// ---- packed f32x2 helpers (sm_103a) ------------------------------------
__device__ __forceinline__ ull pk2(float x, float y) {
    ull r; asm("mov.b64 %0, {%1, %2};" : "=l"(r) : "f"(x), "f"(y)); return r;
}
__device__ __forceinline__ void unpk2(float& lo, float& hi, ull v) {
    asm("mov.b64 {%0, %1}, %2;" : "=f"(lo), "=f"(hi) : "l"(v));
}
__device__ __forceinline__ ull fma2(ull a, ull b, ull c) {
    ull d; asm("fma.rn.f32x2 %0, %1, %2, %3;" : "=l"(d) : "l"(a), "l"(b), "l"(c)); return d;
}
__device__ __forceinline__ ull add2(ull a, ull b) {
    ull d; asm("add.rn.f32x2 %0, %1, %2;" : "=l"(d) : "l"(a), "l"(b)); return d;
}
__device__ __forceinline__ void lds2x64(ull& a, ull& b, unsigned addr) {
    asm volatile("ld.shared.v2.b64 {%0, %1}, [%2];" : "=l"(a), "=l"(b) : "r"(addr));
}

// Branchless sorted insert into ascending 16-list (strict < keeps stream order
// on ties -> matches top_k lowest-index-first tie-breaking).
__device__ __forceinline__ void insert16(float (&bd)[KNN], int (&bi)[KNN],
                                         float d, int ix) {
    bool pk = d < bd[KNN - 1];
#pragma unroll
    for (int k = KNN - 1; k >= 1; --k) {
        bool pk1 = d < bd[k - 1];
        bd[k] = pk ? (pk1 ? bd[k - 1] : d)  : bd[k];
        bi[k] = pk ? (pk1 ? bi[k - 1] : ix) : bi[k];
        pk = pk1;
    }
    if (pk) { bd[0] = d; bi[0] = ix; }
}

__device__ __forceinline__ void flushbuf(float (&bd)[KNN], int (&bi)[KNN],
                                         unsigned bufaddr, int& cnt) {
    for (int u = 0; u < cnt; ++u) {
        float fd; int fi;
        asm volatile("ld.shared.v2.b32 {%0, %1}, [%2];"
                     : "=f"(fd), "=r"(fi)
                     : "r"(bufaddr + (unsigned)(u * BLOCK * 8)));
        insert16(bd, bi, fd, fi);
    }
    cnt = 0;
}

__global__ void __launch_bounds__(BLOCK, 2)
knn_part_kernel(const float* __restrict__ h) {
    __shared__ __align__(16) float smem[TILE * ROWF];   // 34816 B
    __shared__ float sx2[TILE];                         //   512 B
    __shared__ __align__(16) ull sbuf[2 * BUFS * BLOCK]; //  8192 B  (43.5 KB total)

    const int bx   = blockIdx.x;
    const int half = bx & 1;
    const int t2   = bx >> 1;
    const int b    = t2 >> 3;            // NP/QB = 8 query blocks per sample
    const int qblk = (t2 & 7) * QB;
    const int tid  = threadIdx.x;
    const float* hb = h + (size_t)b * NP * DIM;

    const int q0 = qblk + tid;
    const int q1 = qblk + BLOCK + tid;

    // ---- two register-resident packed query vectors + squared norms ----
    ull q0p[DIM / 2], q1p[DIM / 2];
    float x2q0 = 0.0f, x2q1 = 0.0f;
    {
        const float4* g0 = (const float4*)(hb + (size_t)q0 * DIM);
        const float4* g1 = (const float4*)(hb + (size_t)q1 * DIM);
#pragma unroll
        for (int i = 0; i < DIM / 4; i++) {
            float4 v = g0[i];
            x2q0 = fmaf(v.x, v.x, x2q0); x2q0 = fmaf(v.y, v.y, x2q0);
            x2q0 = fmaf(v.z, v.z, x2q0); x2q0 = fmaf(v.w, v.w, x2q0);
            q0p[2 * i] = pk2(v.x, v.y);  q0p[2 * i + 1] = pk2(v.z, v.w);
            float4 w = g1[i];
            x2q1 = fmaf(w.x, w.x, x2q1); x2q1 = fmaf(w.y, w.y, x2q1);
            x2q1 = fmaf(w.z, w.z, x2q1); x2q1 = fmaf(w.w, w.w, x2q1);
            q1p[2 * i] = pk2(w.x, w.y);  q1p[2 * i + 1] = pk2(w.z, w.w);
        }
    }

    float bd0[KNN], bd1[KNN];
    int   bi0[KNN], bi1[KNN];
#pragma unroll
    for (int k = 0; k < KNN; k++) {
        bd0[k] = __int_as_float(0x7f800000); bi0[k] = 0;
        bd1[k] = __int_as_float(0x7f800000); bi1[k] = 0;
    }
    int cnt0 = 0, cnt1 = 0;

    const unsigned sbase = (unsigned)__cvta_generic_to_shared(smem);
    const unsigned bufb  = (unsigned)__cvta_generic_to_shared(sbuf) + tid * 8;
    const unsigned buf0  = bufb;
    const unsigned buf1  = bufb + BUFS * BLOCK * 8;

    const int gbase = half * CAND;

    for (int tt = 0; tt < CAND / TILE; tt++) {
        __syncthreads();
        // cooperative coalesced tile load with row padding
        {
            const float4* gt = (const float4*)(hb + (size_t)(gbase + tt * TILE) * DIM);
#pragma unroll
            for (int i = 0; i < (TILE * DIM / 4) / BLOCK; i++) {  // 16 iters
                int idx = i * BLOCK + tid;
                int row = idx >> 4;
                int col = idx & 15;
                ((float4*)smem)[row * (ROWF / 4) + col] = gt[idx];
            }
        }
        __syncthreads();
        {   // per-row squared norm (one row per thread; TILE == BLOCK)
            const float4* rp = (const float4*)(smem + tid * ROWF);
            float s = 0.0f;
#pragma unroll
            for (int i = 0; i < DIM / 4; i++) {
                float4 v = rp[i];
                s = fmaf(v.x, v.x, s); s = fmaf(v.y, v.y, s);
                s = fmaf(v.z, v.z, s); s = fmaf(v.w, v.w, s);
            }
            sx2[tid] = s;
        }
        __syncthreads();

        unsigned rb = sbase;
        for (int j = 0; j < TILE; j++, rb += ROWB) {
            ull a00 = 0ull, a01 = 0ull, a10 = 0ull, a11 = 0ull;
#pragma unroll
            for (int i = 0; i < 16; i += 2) {     // 16 chunks of 16 B
                ull v0, v1, v2, v3;
                lds2x64(v0, v1, rb + i * 16);
                lds2x64(v2, v3, rb + i * 16 + 16);
                a00 = fma2(q0p[2 * i],     v0, a00);
                a01 = fma2(q0p[2 * i + 1], v1, a01);
                a10 = fma2(q1p[2 * i],     v0, a10);
                a11 = fma2(q1p[2 * i + 1], v1, a11);
                a00 = fma2(q0p[2 * i + 2], v2, a00);
                a01 = fma2(q0p[2 * i + 3], v3, a01);
                a10 = fma2(q1p[2 * i + 2], v2, a10);
                a11 = fma2(q1p[2 * i + 3], v3, a11);
            }
            float l0, h0; unpk2(l0, h0, add2(a00, a01));
            float l1, h1; unpk2(l1, h1, add2(a10, a11));
            const float sj = sx2[j];
            const float d0 = fmaf(-2.0f, l0 + h0, x2q0 + sj);
            const float d1 = fmaf(-2.0f, l1 + h1, x2q1 + sj);
            const int gidx = gbase + tt * TILE + j;

            if (d0 < bd0[KNN - 1]) {   // predicated push into ring buffer
                asm volatile("st.shared.v2.b32 [%0], {%1, %2};"
                             :: "r"(buf0 + (unsigned)(cnt0 * (BLOCK * 8))),
                                "f"(d0), "r"(gidx) : "memory");
                cnt0++;
            }
            if (d1 < bd1[KNN - 1]) {
                asm volatile("st.shared.v2.b32 [%0], {%1, %2};"
                             :: "r"(buf1 + (unsigned)(cnt1 * (BLOCK * 8))),
                                "f"(d1), "r"(gidx) : "memory");
                cnt1++;
            }
            // (cnt0|cnt1) has bit2 set iff either counter reached BUFS=4
            if (__ballot_sync(0xffffffffu, (cnt0 | cnt1) >= BUFS)) {
                flushbuf(bd0, bi0, buf0, cnt0);
                flushbuf(bd1, bi1, buf1, cnt1);
            }
        }
    }
    flushbuf(bd0, bi0, buf0, cnt0);
    flushbuf(bd1, bi1, buf1, cnt1);

    const size_t r0 = (size_t)b * NP + q0;
    const size_t r1 = (size_t)b * NP + q1;
#pragma unroll
    for (int k = 0; k < KNN; k++) {
        g_pd[half][r0][k] = bd0[k];  g_pi[half][r0][k] = bi0[k];
        g_pd[half][r1][k] = bd1[k];  g_pi[half][r1][k] = bi1[k];
    }
}

// Merge the two half-DB sorted-16 lists. Half-0 candidate indices are all
// smaller than half-1's, so <= favors half 0 = lowest-index-first on ties.
__global__ void __launch_bounds__(BLOCK, 8)
knn_merge_kernel(float* __restrict__ out, int write_edges) {
    const int gq = blockIdx.x * BLOCK + threadIdx.x;   // 0..NS*NP-1
    const int b  = gq >> 11;                           // / NP
    const int off = b * NP;
    const size_t o = (size_t)gq * KNN;

    int i = 0, j = 0;
#pragma unroll
    for (int k = 0; k < KNN; k++) {    // i+j=k<=15 so no bounds checks needed
        float d0 = g_pd[0][gq][i], d1 = g_pd[1][gq][j];
        bool take0 = d0 <= d1;
        float dv = take0 ? d0 : d1;
        int   ix = take0 ? g_pi[0][gq][i] : g_pi[1][gq][j];
        i += take0; j += !take0;
        out[o + k] = dv;
        if (write_edges) {
            out[(size_t)NTOT + o + k]     = (float)(ix + off);
            out[(size_t)2 * NTOT + o + k] = (float)gq;        // src = q + b*NP
        }
    }
}

extern "C" void kernel_launch(void* const* d_in, const int* in_sizes, int n_in,
                              void* d_out, int out_size) {
    const float* h = (const float*)d_in[0];
    int write_edges = (out_size >= 3 * NTOT) ? 1 : 0;
    knn_part_kernel<<<NS * (NP / QB) * HALF, BLOCK>>>(h);
    knn_merge_kernel<<<NS * NP / BLOCK, BLOCK>>>((float*)d_out, write_edges);
}